// round 5
// baseline (speedup 1.0000x reference)
#include <cuda_runtime.h>
#include <cuda_fp16.h>

#define NX    512
#define NPTS  32768
#define CCH   64
#define NB    4
#define PLANE (NX * NX)
#define BVOL  (PLANE * CCH)
#define NTB   4096                 // transpose blocks per batch (PLANE/64)
#define NGB   1024                 // gather blocks per batch (NPTS/32)

// NHWC fp16 scratch (b, py, px, c). 134 MB; one batch slice = 33.5 MB (L2-fits).
__device__ __half g_xt[(size_t)NB * BVOL];

// ---------------------------------------------------------------------------
// Transpose role: one 64-pixel x 64-channel tile of batch tb, fp32->fp16.
// ---------------------------------------------------------------------------
__device__ __forceinline__ void do_transpose(float* sm, const float* __restrict__ x,
                                             int tb, int tile)
{
    float (*s)[66] = (float(*)[66])sm;          // [pixel][channel]
    const int p0 = tile * 64;
    const int pl = threadIdx.x & 63;
    const int c0 = threadIdx.x >> 6;

    const float* xb = x + (size_t)tb * BVOL;
    #pragma unroll
    for (int c = c0; c < 64; c += 4)
        s[pl][c] = __ldcs(xb + (size_t)c * PLANE + p0 + pl);   // streaming reads

    __syncthreads();

    __half* yb = g_xt + (size_t)tb * BVOL + (size_t)p0 * CCH;
    #pragma unroll
    for (int i = threadIdx.x; i < 64 * 32; i += 256) {
        const int p  = i >> 5;
        const int cp = i & 31;
        const float2 v = *(const float2*)&s[p][2 * cp];
        ((__half2*)(yb + (size_t)p * CCH))[cp] = __floats2half2_rn(v.x, v.y);
    }   // cached store: to be read from L2 by the next launch's gather
}

// ---------------------------------------------------------------------------
// Gather role: 32 consecutive points of batch gb.
// ---------------------------------------------------------------------------
__device__ __forceinline__ void do_gather(float* sm, const float* __restrict__ coords,
                                          float* __restrict__ out, int gb, int gblk)
{
    float  (*s_w)[9]    = (float(*)[9])sm;                 // 288 floats
    int    (*s_off)[9]  = (int(*)[9])(sm + 288);           // 288 floats
    float2 (*s_out)[33] = (float2(*)[33])(sm + 576);       // 2112 floats

    const int n0  = gblk * 32;
    const int tid = threadIdx.x;

    if (tid < 32) {
        const int   n    = n0 + tid;
        const float cy   = coords[((size_t)gb * NPTS + n) * 2 + 0];
        const float cx   = coords[((size_t)gb * NPTS + n) * 2 + 1];
        const float posx = cx * 511.0f;
        const float posy = cy * 511.0f;
        const float rx   = rintf(posx);       // jnp.round = half-to-even
        const float ry   = rintf(posy);

        float wx[3] = {0.f, 0.f, 0.f};
        float wy[3] = {0.f, 0.f, 0.f};
        #pragma unroll
        for (int j = 0; j < 9; j++) {
            const float o  = 1.5f - 0.375f * (float)j;           // off_n[j]
            const float px = fminf(fmaxf(rx - o, 0.f), 512.f);   // clip hi = nx (ref quirk)
            const float py = fminf(fmaxf(ry - o, 0.f), 512.f);
            const float dx = px - posx;
            const float dy = py - posy;
            wx[j / 3] += __expf(-2.f * dx * dx);  // normal const cancels in norm
            wy[j / 3] += __expf(-2.f * dy * dy);
        }

        float w9[9];
        float s = 0.f;
        #pragma unroll
        for (int a = 0; a < 3; a++)
            #pragma unroll
            for (int c2 = 0; c2 < 3; c2++) {
                const float w = wx[a] * wy[c2];
                w9[a * 3 + c2] = w;
                s += w;
            }
        const float inv = 1.0f / s;

        const int irx = (int)rx;
        const int iry = (int)ry;
        int ixs[3], iys[3];
        #pragma unroll
        for (int a = 0; a < 3; a++) {
            ixs[a] = min(max(irx + 1 - a, 0), NX - 1);
            iys[a] = min(max(iry + 1 - a, 0), NX - 1);
        }

        #pragma unroll
        for (int a = 0; a < 3; a++)
            #pragma unroll
            for (int c2 = 0; c2 < 3; c2++) {
                s_w[tid][a * 3 + c2]   = w9[a * 3 + c2] * inv;
                s_off[tid][a * 3 + c2] = (ixs[a] * NX + iys[c2]) * CCH;
            }
    }
    __syncthreads();

    const int lane = tid & 31;
    const int warp = tid >> 5;
    const __half* base = g_xt + (size_t)gb * BVOL + 2 * lane;

    #pragma unroll
    for (int qq = 0; qq < 4; qq += 2) {
        const int q0 = warp * 4 + qq;
        const int q1 = q0 + 1;
        float2 a0 = make_float2(0.f, 0.f);
        float2 a1 = make_float2(0.f, 0.f);
        #pragma unroll
        for (int k = 0; k < 9; k++) {
            const float2 v0 = __half22float2(*(const __half2*)(base + s_off[q0][k]));
            const float2 v1 = __half22float2(*(const __half2*)(base + s_off[q1][k]));
            const float  w0 = s_w[q0][k];
            const float  w1 = s_w[q1][k];
            a0.x += w0 * v0.x;  a0.y += w0 * v0.y;
            a1.x += w1 * v1.x;  a1.y += w1 * v1.y;
        }
        s_out[lane][q0] = a0;
        s_out[lane][q1] = a1;
    }
    __syncthreads();

    float* ob = out + (size_t)gb * CCH * NPTS + n0;
    #pragma unroll
    for (int i = tid; i < CCH * 32; i += 256) {
        const int j = i & 31;
        const int c = i >> 5;
        const float2 v = s_out[c >> 1][j];
        __stcs(ob + (size_t)c * NPTS + j, (c & 1) ? v.y : v.x);  // streaming out
    }
}

// ---------------------------------------------------------------------------
// Fused launch. tb = batch to transpose (-1: none), gb = batch to gather
// (-1: none). Mixed launches interleave roles: every 5th block gathers, so
// both roles occupy every wave concurrently.
// ---------------------------------------------------------------------------
__global__ __launch_bounds__(256) void fused_kernel(
    const float* __restrict__ x,
    const float* __restrict__ coords,
    float*       __restrict__ out,
    int tb, int gb)
{
    __shared__ __align__(16) float sm[64 * 66];

    if (gb < 0) {
        do_transpose(sm, x, tb, blockIdx.x);
    } else if (tb < 0) {
        do_gather(sm, coords, out, gb, blockIdx.x);
    } else {
        const int g = blockIdx.x / 5;
        const int r = blockIdx.x % 5;
        if (r == 4) do_gather(sm, coords, out, gb, g);           // 1024 blocks
        else        do_transpose(sm, x, tb, g * 4 + r);          // 4096 blocks
    }
}

extern "C" void kernel_launch(void* const* d_in, const int* in_sizes, int n_in,
                              void* d_out, int out_size) {
    const float* x      = (const float*)d_in[0];
    const float* coords = (const float*)d_in[1];
    if (n_in >= 2 && in_sizes[0] == NB * NPTS * 2) {   // defensive swap
        const float* t = x; x = coords; coords = t;
    }
    float* out = (float*)d_out;

    fused_kernel<<<NTB, 256>>>(x, coords, out, 0, -1);            // T0
    for (int k = 1; k < NB; k++)
        fused_kernel<<<NTB + NGB, 256>>>(x, coords, out, k, k - 1); // Tk || G(k-1)
    fused_kernel<<<NGB, 256>>>(x, coords, out, -1, NB - 1);       // G3
}

// round 6
// speedup vs baseline: 1.0345x; 1.0345x over previous
#include <cuda_runtime.h>
#include <cuda_fp16.h>

#define NX    512
#define NPTS  32768
#define CCH   64
#define NB    4
#define PLANE (NX * NX)
#define BVOL  (PLANE * CCH)

// NHWC fp16 scratch (b, py, px, c). One batch slice = 33.5 MB -> fits L2.
__device__ __half g_xt[(size_t)NB * BVOL];

// ---------------------------------------------------------------------------
// Transpose: one batch, NCHW fp32 -> NHWC fp16. Tile = 64 px x 64 ch.
// Grid 4096 x 256. x reads are evict-first so prior scratch stays in L2.
// ---------------------------------------------------------------------------
__global__ __launch_bounds__(256) void transpose_kernel(const float* __restrict__ x,
                                                        int b)
{
    __shared__ float s[64][66];               // [pixel][channel]

    const int p0 = blockIdx.x * 64;
    const int pl = threadIdx.x & 63;
    const int c0 = threadIdx.x >> 6;

    const float* xb = x + (size_t)b * BVOL;
    #pragma unroll
    for (int c = c0; c < 64; c += 4)
        s[pl][c] = __ldcs(xb + (size_t)c * PLANE + p0 + pl);   // streaming reads

    __syncthreads();

    __half* yb = g_xt + (size_t)b * BVOL + (size_t)p0 * CCH;
    #pragma unroll
    for (int i = threadIdx.x; i < 64 * 32; i += 256) {
        const int p  = i >> 5;                // pixel
        const int cp = i & 31;                // channel pair
        const float2 v = *(const float2*)&s[p][2 * cp];
        ((__half2*)(yb + (size_t)p * CCH))[cp] = __floats2half2_rn(v.x, v.y);
    }   // default (cached) stores: consumed from L2 by the next launch
}

// ---------------------------------------------------------------------------
// Gather: one batch. Block = 256 threads, 32 consecutive points.
// Warp 0 computes weights; each warp then does 4 points, lane = channel pair.
// All 9 taps x 2 points preloaded into registers before any FMA (MLP=18).
// ---------------------------------------------------------------------------
__global__ __launch_bounds__(256) void gather_kernel(const float* __restrict__ coords,
                                                     float* __restrict__ out,
                                                     int b)
{
    __shared__ float  s_w[32][9];
    __shared__ int    s_off[32][9];       // half-element offset in NHWC batch
    __shared__ float2 s_out[32][33];      // [channel pair][point]

    const int n0  = blockIdx.x * 32;
    const int tid = threadIdx.x;

    // ---- Phase 1: per-point normalized 3x3 weights + offsets ----
    if (tid < 32) {
        const int   n    = n0 + tid;
        const float cy   = coords[((size_t)b * NPTS + n) * 2 + 0];
        const float cx   = coords[((size_t)b * NPTS + n) * 2 + 1];
        const float posx = cx * 511.0f;
        const float posy = cy * 511.0f;
        const float rx   = rintf(posx);       // jnp.round = half-to-even
        const float ry   = rintf(posy);

        float wx[3] = {0.f, 0.f, 0.f};
        float wy[3] = {0.f, 0.f, 0.f};
        #pragma unroll
        for (int j = 0; j < 9; j++) {
            const float o  = 1.5f - 0.375f * (float)j;           // off_n[j]
            const float px = fminf(fmaxf(rx - o, 0.f), 512.f);   // clip hi = nx (ref quirk)
            const float py = fminf(fmaxf(ry - o, 0.f), 512.f);
            const float dx = px - posx;
            const float dy = py - posy;
            wx[j / 3] += __expf(-2.f * dx * dx);  // normal const cancels in norm
            wy[j / 3] += __expf(-2.f * dy * dy);
        }

        float w9[9];
        float s = 0.f;
        #pragma unroll
        for (int a = 0; a < 3; a++)
            #pragma unroll
            for (int c2 = 0; c2 < 3; c2++) {
                const float w = wx[a] * wy[c2];
                w9[a * 3 + c2] = w;
                s += w;
            }
        const float inv = 1.0f / s;

        const int irx = (int)rx;
        const int iry = (int)ry;
        int ixs[3], iys[3];
        #pragma unroll
        for (int a = 0; a < 3; a++) {
            ixs[a] = min(max(irx + 1 - a, 0), NX - 1);
            iys[a] = min(max(iry + 1 - a, 0), NX - 1);
        }

        #pragma unroll
        for (int a = 0; a < 3; a++)
            #pragma unroll
            for (int c2 = 0; c2 < 3; c2++) {
                s_w[tid][a * 3 + c2]   = w9[a * 3 + c2] * inv;
                s_off[tid][a * 3 + c2] = (ixs[a] * NX + iys[c2]) * CCH;
            }
    }
    __syncthreads();

    // ---- Phase 2: dense fp16 NHWC gather, loads before math ----
    const int lane = tid & 31;
    const int warp = tid >> 5;
    const __half* base = g_xt + (size_t)b * BVOL + 2 * lane;

    #pragma unroll
    for (int qq = 0; qq < 4; qq += 2) {
        const int q0 = warp * 4 + qq;
        const int q1 = q0 + 1;

        unsigned v0[9], v1[9];
        #pragma unroll
        for (int k = 0; k < 9; k++)
            v0[k] = *(const unsigned*)(base + s_off[q0][k]);
        #pragma unroll
        for (int k = 0; k < 9; k++)
            v1[k] = *(const unsigned*)(base + s_off[q1][k]);

        float2 a0 = make_float2(0.f, 0.f);
        float2 a1 = make_float2(0.f, 0.f);
        #pragma unroll
        for (int k = 0; k < 9; k++) {
            const float2 f0 = __half22float2(*(const __half2*)&v0[k]);
            const float2 f1 = __half22float2(*(const __half2*)&v1[k]);
            const float  w0 = s_w[q0][k];
            const float  w1 = s_w[q1][k];
            a0.x += w0 * f0.x;  a0.y += w0 * f0.y;
            a1.x += w1 * f1.x;  a1.y += w1 * f1.y;
        }
        s_out[lane][q0] = a0;
        s_out[lane][q1] = a1;
    }
    __syncthreads();

    // ---- Phase 3: coalesced (c, n) streaming writes ----
    float* ob = out + (size_t)b * CCH * NPTS + n0;
    #pragma unroll
    for (int i = tid; i < CCH * 32; i += 256) {
        const int j = i & 31;
        const int c = i >> 5;
        const float2 v = s_out[c >> 1][j];
        __stcs(ob + (size_t)c * NPTS + j, (c & 1) ? v.y : v.x);
    }
}

extern "C" void kernel_launch(void* const* d_in, const int* in_sizes, int n_in,
                              void* d_out, int out_size) {
    const float* x      = (const float*)d_in[0];
    const float* coords = (const float*)d_in[1];
    if (n_in >= 2 && in_sizes[0] == NB * NPTS * 2) {   // defensive swap
        const float* t = x; x = coords; coords = t;
    }
    float* out = (float*)d_out;

    // Per-batch T,G pairs: G_k consumes scratch written by the launch right
    // before it, so its reads hit L2 (33.5 MB slice, x reads were evict-first).
    for (int b = 0; b < NB; b++) {
        transpose_kernel<<<PLANE / 64, 256>>>(x, b);
        gather_kernel<<<NPTS / 32, 256>>>(coords, out, b);
    }
}

// round 7
// speedup vs baseline: 1.2951x; 1.2519x over previous
#include <cuda_runtime.h>
#include <cuda_fp16.h>

#define NX    512
#define NPTS  32768
#define CCH   64
#define NB    4
#define PLANE (NX * NX)
#define BVOL  (PLANE * CCH)

// NHWC fp16 scratch (b, py, px, c). 134 MB.
__device__ __half g_xt[(size_t)NB * BVOL];

// ---------------------------------------------------------------------------
// Kernel 1: NCHW fp32 -> NHWC fp16. Tile = 64 px x 64 ch, 256 threads.
// Load phase: 4x LDG.128 per thread (float4 along pixels), smem [ch][px].
// Pack phase: warp writes one pixel's 64 channels as 32 half2 (128B store).
// ---------------------------------------------------------------------------
__global__ __launch_bounds__(256) void transpose_kernel(const float* __restrict__ x)
{
    __shared__ float s[64][65];               // [channel][pixel], odd stride

    const int tile = blockIdx.x;
    const int b    = tile >> 12;              // 4096 tiles per batch
    const int p0   = (tile & 4095) * 64;

    const int slot = threadIdx.x & 15;        // float4 slot (4 px each)
    const int c0   = threadIdx.x >> 4;        // 0..15

    const float* xb = x + (size_t)b * BVOL;
    #pragma unroll
    for (int c = c0; c < 64; c += 16) {
        const float4 v = __ldcs((const float4*)(xb + (size_t)c * PLANE + p0 + slot * 4));
        s[c][slot * 4 + 0] = v.x;
        s[c][slot * 4 + 1] = v.y;
        s[c][slot * 4 + 2] = v.z;
        s[c][slot * 4 + 3] = v.w;
    }
    __syncthreads();

    __half* yb = g_xt + (size_t)b * BVOL + (size_t)p0 * CCH;
    #pragma unroll
    for (int i = threadIdx.x; i < 64 * 32; i += 256) {
        const int p  = i >> 5;                // pixel
        const int cp = i & 31;                // channel pair
        ((__half2*)(yb + (size_t)p * CCH))[cp] =
            __floats2half2_rn(s[2 * cp][p], s[2 * cp + 1][p]);
    }
}

// ---------------------------------------------------------------------------
// Kernel 2: gather, all batches. Block = 256 threads, 32 consecutive points.
// Warp 0 computes per-point weights/offsets into 16B-aligned 48B records;
// each warp then does 4 points (2 at a time), lane = channel pair.
// Records fetched via LDS.128 (3 per point), taps preloaded for MLP=18.
// ---------------------------------------------------------------------------
__global__ __launch_bounds__(256) void gather_kernel(
    const float* __restrict__ coords,
    float*       __restrict__ out)
{
    __shared__ __align__(16) float s_w[32][12];    // 9 used, 48B rows
    __shared__ __align__(16) int   s_off[32][12];  // half-elem offsets in batch
    __shared__ float2 s_out[32][33];

    const int p0g = blockIdx.x * 32;
    const int b   = p0g / NPTS;
    const int n0  = p0g % NPTS;
    const int tid = threadIdx.x;

    // ---- Phase 1: weights (identical math to all passing kernels) ----
    if (tid < 32) {
        const int   n    = n0 + tid;
        const float cy   = coords[((size_t)b * NPTS + n) * 2 + 0];
        const float cx   = coords[((size_t)b * NPTS + n) * 2 + 1];
        const float posx = cx * 511.0f;
        const float posy = cy * 511.0f;
        const float rx   = rintf(posx);       // jnp.round = half-to-even
        const float ry   = rintf(posy);

        float wx[3] = {0.f, 0.f, 0.f};
        float wy[3] = {0.f, 0.f, 0.f};
        #pragma unroll
        for (int j = 0; j < 9; j++) {
            const float o  = 1.5f - 0.375f * (float)j;           // off_n[j]
            const float px = fminf(fmaxf(rx - o, 0.f), 512.f);   // clip hi = nx (ref quirk)
            const float py = fminf(fmaxf(ry - o, 0.f), 512.f);
            const float dx = px - posx;
            const float dy = py - posy;
            wx[j / 3] += __expf(-2.f * dx * dx);  // normal const cancels in norm
            wy[j / 3] += __expf(-2.f * dy * dy);
        }

        float w9[9];
        float s = 0.f;
        #pragma unroll
        for (int a = 0; a < 3; a++)
            #pragma unroll
            for (int c2 = 0; c2 < 3; c2++) {
                const float w = wx[a] * wy[c2];
                w9[a * 3 + c2] = w;
                s += w;
            }
        const float inv = 1.0f / s;

        const int irx = (int)rx;
        const int iry = (int)ry;
        int ixs[3], iys[3];
        #pragma unroll
        for (int a = 0; a < 3; a++) {
            ixs[a] = min(max(irx + 1 - a, 0), NX - 1);
            iys[a] = min(max(iry + 1 - a, 0), NX - 1);
        }

        #pragma unroll
        for (int a = 0; a < 3; a++)
            #pragma unroll
            for (int c2 = 0; c2 < 3; c2++) {
                s_w[tid][a * 3 + c2]   = w9[a * 3 + c2] * inv;
                s_off[tid][a * 3 + c2] = (ixs[a] * NX + iys[c2]) * CCH;
            }
    }
    __syncthreads();

    // ---- Phase 2: dense fp16 NHWC gather ----
    const int lane = tid & 31;
    const int warp = tid >> 5;
    const __half* base = g_xt + (size_t)b * BVOL + 2 * lane;

    #pragma unroll
    for (int qq = 0; qq < 4; qq += 2) {
        const int q0 = warp * 4 + qq;
        const int q1 = q0 + 1;

        // Vector-load the two records: 3x LDS.128 each for offsets & weights.
        const int4 oA0 = *(const int4*)&s_off[q0][0];
        const int4 oB0 = *(const int4*)&s_off[q0][4];
        const int  o80 = s_off[q0][8];
        const int4 oA1 = *(const int4*)&s_off[q1][0];
        const int4 oB1 = *(const int4*)&s_off[q1][4];
        const int  o81 = s_off[q1][8];
        const int off0[9] = {oA0.x, oA0.y, oA0.z, oA0.w, oB0.x, oB0.y, oB0.z, oB0.w, o80};
        const int off1[9] = {oA1.x, oA1.y, oA1.z, oA1.w, oB1.x, oB1.y, oB1.z, oB1.w, o81};

        const float4 wA0 = *(const float4*)&s_w[q0][0];
        const float4 wB0 = *(const float4*)&s_w[q0][4];
        const float  w80 = s_w[q0][8];
        const float4 wA1 = *(const float4*)&s_w[q1][0];
        const float4 wB1 = *(const float4*)&s_w[q1][4];
        const float  w81 = s_w[q1][8];
        const float w0[9] = {wA0.x, wA0.y, wA0.z, wA0.w, wB0.x, wB0.y, wB0.z, wB0.w, w80};
        const float w1[9] = {wA1.x, wA1.y, wA1.z, wA1.w, wB1.x, wB1.y, wB1.z, wB1.w, w81};

        unsigned v0[9], v1[9];
        #pragma unroll
        for (int k = 0; k < 9; k++)
            v0[k] = *(const unsigned*)(base + off0[k]);
        #pragma unroll
        for (int k = 0; k < 9; k++)
            v1[k] = *(const unsigned*)(base + off1[k]);

        float2 a0 = make_float2(0.f, 0.f);
        float2 a1 = make_float2(0.f, 0.f);
        #pragma unroll
        for (int k = 0; k < 9; k++) {
            const float2 f0 = __half22float2(*(const __half2*)&v0[k]);
            const float2 f1 = __half22float2(*(const __half2*)&v1[k]);
            a0.x += w0[k] * f0.x;  a0.y += w0[k] * f0.y;
            a1.x += w1[k] * f1.x;  a1.y += w1[k] * f1.y;
        }
        s_out[lane][q0] = a0;
        s_out[lane][q1] = a1;
    }
    __syncthreads();

    // ---- Phase 3: coalesced (c, n) writes ----
    float* ob = out + (size_t)b * CCH * NPTS + n0;
    #pragma unroll
    for (int i = tid; i < CCH * 32; i += 256) {
        const int j = i & 31;
        const int c = i >> 5;
        const float2 v = s_out[c >> 1][j];
        __stcs(ob + (size_t)c * NPTS + j, (c & 1) ? v.y : v.x);
    }
}

extern "C" void kernel_launch(void* const* d_in, const int* in_sizes, int n_in,
                              void* d_out, int out_size) {
    const float* x      = (const float*)d_in[0];
    const float* coords = (const float*)d_in[1];
    if (n_in >= 2 && in_sizes[0] == NB * NPTS * 2) {   // defensive swap
        const float* t = x; x = coords; coords = t;
    }
    float* out = (float*)d_out;

    transpose_kernel<<<NB * (PLANE / 64), 256>>>(x);
    gather_kernel<<<(NB * NPTS) / 32, 256>>>(coords, out);
}